// round 2
// baseline (speedup 1.0000x reference)
#include <cuda_runtime.h>
#include <cuda_bf16.h>
#include <math.h>
#include <float.h>

// Problem shape (LG_MGC_2731599200834): B=256, L=576, D=1024, k=24
#define D_DIM 1024
#define MAX_B 256
#define MAX_L 576
#define MAX_K 64

// Scratch: per-(batch, token) ranking score. Ranking by dot * rsqrt(|t|^2)
// is order-equivalent to the reference cosine sim (n_i > 0 scalar per batch,
// eps clamp never active for these magnitudes).
__device__ float g_sims[MAX_B * MAX_L];

// ---------------------------------------------------------------------------
// Kernel A: one streaming pass over image_feats.
// grid = (ceil(L/8), B), block = 256 threads (8 warps). Each warp computes
// one token's dot(i_feats[b], token) and |token|^2.
// ---------------------------------------------------------------------------
__global__ void __launch_bounds__(256)
sims_kernel(const float* __restrict__ i_feats,
            const float* __restrict__ image_feats,
            int L)
{
    __shared__ float4 s_i[D_DIM / 4];   // 4 KB: i_feats row for this batch

    const int b    = blockIdx.y;
    const int tid  = threadIdx.x;
    const int warp = tid >> 5;
    const int lane = tid & 31;

    // 256 threads load 256 float4 = 1024 floats (coalesced)
    s_i[tid] = reinterpret_cast<const float4*>(i_feats + (size_t)b * D_DIM)[tid];
    __syncthreads();

    const int token = blockIdx.x * 8 + warp;
    if (token >= L) return;

    const float4* __restrict__ tok = reinterpret_cast<const float4*>(
        image_feats + ((size_t)b * L + token) * D_DIM) + lane;

    float dot = 0.f, nt2 = 0.f;
    #pragma unroll
    for (int j = 0; j < D_DIM / (32 * 4); ++j) {      // 8 iterations
        float4 v = __ldg(tok + j * 32);               // coalesced 128B/warp/step
        float4 a = s_i[lane + j * 32];
        dot += a.x * v.x + a.y * v.y + a.z * v.z + a.w * v.w;
        nt2 += v.x * v.x + v.y * v.y + v.z * v.z + v.w * v.w;
    }

    // warp reduction
    #pragma unroll
    for (int off = 16; off > 0; off >>= 1) {
        dot += __shfl_xor_sync(0xffffffffu, dot, off);
        nt2 += __shfl_xor_sync(0xffffffffu, nt2, off);
    }

    if (lane == 0)
        g_sims[b * L + token] = dot * rsqrtf(fmaxf(nt2, 1e-16f));
}

// ---------------------------------------------------------------------------
// Kernel B: per-batch bottom-k selection + gather-mean.
// grid = B, block = 256 threads. Warp 0 extracts the k smallest sims
// (tie -> lower index, matching top_k stability); then all threads
// accumulate the k tokens (float4, coalesced) and write the mean.
// ---------------------------------------------------------------------------
__global__ void __launch_bounds__(256)
select_mean_kernel(const float* __restrict__ image_feats,
                   const int* __restrict__ k_ptr,
                   float* __restrict__ out,
                   int L)
{
    __shared__ float s_sims[MAX_L];
    __shared__ int   s_idx[MAX_K];

    const int b   = blockIdx.x;
    const int tid = threadIdx.x;

    int k = *k_ptr;
    if (k < 1) k = 1;
    if (k > MAX_K) k = MAX_K;

    for (int i = tid; i < L; i += blockDim.x)
        s_sims[i] = g_sims[b * L + i];
    __syncthreads();

    if (tid < 32) {
        const int lane = tid;
        for (int iter = 0; iter < k; ++iter) {
            float mv = FLT_MAX;
            int   mi = -1;
            for (int i = lane; i < L; i += 32) {
                float v = s_sims[i];
                if (v < mv) { mv = v; mi = i; }
            }
            // warp arg-min reduce, ties -> smaller index
            #pragma unroll
            for (int off = 16; off > 0; off >>= 1) {
                float ov = __shfl_xor_sync(0xffffffffu, mv, off);
                int   oi = __shfl_xor_sync(0xffffffffu, mi, off);
                if (ov < mv || (ov == mv && oi >= 0 && (mi < 0 || oi < mi))) {
                    mv = ov; mi = oi;
                }
            }
            if (lane == 0) {
                s_idx[iter]   = mi;
                s_sims[mi]    = FLT_MAX;   // exclude from next iterations
            }
            __syncwarp();
        }
    }
    __syncthreads();

    // Gather-mean: thread t owns float4 dims [4t, 4t+4). 256 threads x 16B
    // per token = fully coalesced 4KB bursts.
    float4 acc = make_float4(0.f, 0.f, 0.f, 0.f);
    for (int j = 0; j < k; ++j) {
        const int idx = s_idx[j];
        float4 v = reinterpret_cast<const float4*>(
            image_feats + ((size_t)b * L + idx) * D_DIM)[tid];
        acc.x += v.x; acc.y += v.y; acc.z += v.z; acc.w += v.w;
    }
    const float inv_k = 1.0f / (float)k;
    acc.x *= inv_k; acc.y *= inv_k; acc.z *= inv_k; acc.w *= inv_k;
    reinterpret_cast<float4*>(out + (size_t)b * D_DIM)[tid] = acc;
}

// ---------------------------------------------------------------------------
extern "C" void kernel_launch(void* const* d_in, const int* in_sizes, int n_in,
                              void* d_out, int out_size)
{
    const float* i_feats     = (const float*)d_in[0];   // [B, D]
    const float* image_feats = (const float*)d_in[1];   // [B, L, D]
    const int*   k_ptr       = (const int*)d_in[2];     // scalar k

    const int B = in_sizes[0] / D_DIM;                  // 256
    const int L = in_sizes[1] / in_sizes[0];            // 576

    dim3 gridA((L + 7) / 8, B);
    sims_kernel<<<gridA, 256>>>(i_feats, image_feats, L);

    select_mean_kernel<<<B, 256>>>(image_feats, k_ptr, (float*)d_out, L);
}